// round 1
// baseline (speedup 1.0000x reference)
#include <cuda_runtime.h>
#include <cuda_bf16.h>

#define BN 8192
#define MARGIN 1.0f
#define TI 256        // threads per block == i-rows per block
#define TJ 512        // j entries per shared-memory tile
#define GX (BN / TI)  // 32
#define GY (BN / TJ)  // 16

// Scratch / accumulators (allocation-free: __device__ globals)
__device__ float g_sum;
__device__ int   g_cnt;
__device__ int   g_nc;
__device__ float c_risk[BN];
__device__ float c_time[BN];

__global__ void k_zero() {
    g_sum = 0.0f;
    g_cnt = 0;
    g_nc  = 0;
}

// Compact rows with event==1 into c_risk/c_time (order irrelevant for the sum).
__global__ void k_compact(const float* __restrict__ risk,
                          const float* __restrict__ timev,
                          const int*   __restrict__ event) {
    int idx = blockIdx.x * blockDim.x + threadIdx.x;
    if (idx >= BN) return;                      // BN % 32 == 0, warps stay full
    bool p = (event[idx] == 1);
    unsigned m = __ballot_sync(0xFFFFFFFFu, p);
    int lane   = threadIdx.x & 31;
    int leader = __ffs(m) - 1;                  // m==0 -> leader=-1, no writes
    int base = 0;
    if (m != 0u && lane == leader)
        base = atomicAdd(&g_nc, __popc(m));
    base = __shfl_sync(0xFFFFFFFFu, base, (leader < 0 ? 0 : leader));
    if (p) {
        int pos = base + __popc(m & ((1u << lane) - 1u));
        c_risk[pos] = risk[idx];
        c_time[pos] = timev[idx];
    }
}

__global__ void k_main(const float* __restrict__ risk,
                       const float* __restrict__ timev) {
    __shared__ float2 sj[TJ];

    const int nc = g_nc;
    // Uniform early exit for blocks entirely past the compacted rows
    if (blockIdx.x * TI >= nc) return;

    // Stage this block's j-tile: (risk_j, time_j)
    const int j0 = blockIdx.y * TJ;
    for (int t = threadIdx.x; t < TJ; t += TI)
        sj[t] = make_float2(risk[j0 + t], timev[j0 + t]);
    __syncthreads();

    const int i = blockIdx.x * TI + threadIdx.x;

    float s[4] = {0.f, 0.f, 0.f, 0.f};
    int   c[4] = {0, 0, 0, 0};

    if (i < nc) {
        const float pr = MARGIN + c_risk[i];   // hinge = max(pr - risk_j, 0)
        const float ti = c_time[i];
        for (int j = 0; j < TJ; j += 4) {
            #pragma unroll
            for (int u = 0; u < 4; ++u) {
                float2 v = sj[j + u];
                bool  m = (ti < v.y);
                float h = fmaxf(pr - v.x, 0.0f);
                s[u] += m ? h : 0.0f;
                c[u] += m ? 1 : 0;
            }
        }
    }

    float ssum = (s[0] + s[1]) + (s[2] + s[3]);
    int   csum = (c[0] + c[1]) + (c[2] + c[3]);

    // Warp reduce
    #pragma unroll
    for (int o = 16; o > 0; o >>= 1) {
        ssum += __shfl_down_sync(0xFFFFFFFFu, ssum, o);
        csum += __shfl_down_sync(0xFFFFFFFFu, csum, o);
    }

    __shared__ float ws[TI / 32];
    __shared__ int   wc[TI / 32];
    int w = threadIdx.x >> 5, l = threadIdx.x & 31;
    if (l == 0) { ws[w] = ssum; wc[w] = csum; }
    __syncthreads();
    if (w == 0) {
        ssum = (l < TI / 32) ? ws[l] : 0.0f;
        csum = (l < TI / 32) ? wc[l] : 0;
        #pragma unroll
        for (int o = (TI / 64); o > 0; o >>= 1) {
            ssum += __shfl_down_sync(0xFFFFFFFFu, ssum, o);
            csum += __shfl_down_sync(0xFFFFFFFFu, csum, o);
        }
        if (l == 0) {
            atomicAdd(&g_sum, ssum);
            atomicAdd(&g_cnt, csum);
        }
    }
}

__global__ void k_final(float* __restrict__ out) {
    out[0] = (g_cnt == 0) ? 0.0f : g_sum / (float)g_cnt;
}

extern "C" void kernel_launch(void* const* d_in, const int* in_sizes, int n_in,
                              void* d_out, int out_size) {
    // metadata order: z (unused), risk, time, event
    const float* risk  = (const float*)d_in[1];
    const float* timev = (const float*)d_in[2];
    const int*   event = (const int*)d_in[3];
    float* out = (float*)d_out;

    k_zero<<<1, 1>>>();
    k_compact<<<BN / 256, 256>>>(risk, timev, event);
    dim3 grid(GX, GY);
    k_main<<<grid, TI>>>(risk, timev);
    k_final<<<1, 1>>>(out);
}